// round 4
// baseline (speedup 1.0000x reference)
#include <cuda_runtime.h>

#define NBATCH 16
#define PPTS   1024
#define NP     (NBATCH*PPTS)   // 16384 points
#define KNN    16
#define DIMS   3
#define C_IN   128
#define C_MID  64
#define C_CAT  192             // C_MID + C_IN
#define C_OUT  256
#define DMUL   2
#define KK2    256             // KNN*KNN
#define EPSV   1e-5f

// ---------------- device scratch (no allocs allowed) ----------------
__device__ float g_lift[(size_t)NP*KNN*C_MID];   // ~67 MB: relu(MLP-lifted features)
__device__ float g_X[(size_t)NP*KK2];            // ~17 MB: X-transform matrices
__device__ float g_pre[(size_t)NP*C_OUT];        // ~17 MB: pre-BN relu output
__device__ float g_pwT[(C_CAT*DMUL)*C_OUT];      // transposed pointwise weights [384][256]
__device__ float g_stats[2*C_OUT];               // per-channel sum / sumsq
__device__ float g_scale[C_OUT];
__device__ float g_shift[C_OUT];

// ---------------- prep: transpose pw_w, zero stats ----------------
__global__ void k_prep(const float* __restrict__ pww) {
    int idx = blockIdx.x * 256 + threadIdx.x;
    if (idx < C_OUT * (C_CAT*DMUL)) {
        int o = idx / (C_CAT*DMUL);
        int j = idx % (C_CAT*DMUL);
        g_pwT[j*C_OUT + o] = pww[idx];
    }
    if (idx < 2*C_OUT) g_stats[idx] = 0.0f;
}

// ---------------- stage 1: point-lifting MLP -> g_lift ----------------
// block = 256 threads = 4 points x 64 channels
__global__ void k_lift(const float* __restrict__ rep, const float* __restrict__ pts,
                       const float* __restrict__ d1w, const float* __restrict__ d1b,
                       const float* __restrict__ d2w, const float* __restrict__ d2b) {
    __shared__ float d1s[DIMS*C_MID];
    __shared__ float d1bs[C_MID];
    __shared__ float d2s[C_MID*C_MID];
    __shared__ float d2bs[C_MID];
    __shared__ float pls[4][KNN*DIMS];   // r = k*DIMS + d (consistent within this kernel)
    __shared__ float hs[4][KNN][C_MID];

    int tid = threadIdx.x;
    for (int i = tid; i < DIMS*C_MID; i += 256) d1s[i] = d1w[i];
    for (int i = tid; i < C_MID*C_MID; i += 256) d2s[i] = d2w[i];
    if (tid < C_MID) { d1bs[tid] = d1b[tid]; d2bs[tid] = d2b[tid]; }

    int lp = tid >> 6;          // local point 0..3
    int c  = tid & 63;          // channel 0..63
    int pt = blockIdx.x * 4 + lp;

    if (c < KNN*DIMS) {
        int k = c / DIMS, d = c % DIMS;
        pls[lp][c] = pts[((size_t)pt*KNN + k)*DIMS + d] - rep[(size_t)pt*DIMS + d];
    }
    __syncthreads();

    // h = relu(pl @ d1 + b1)
    #pragma unroll 4
    for (int k = 0; k < KNN; k++) {
        float acc = d1bs[c];
        #pragma unroll
        for (int d = 0; d < DIMS; d++) acc += pls[lp][k*DIMS+d] * d1s[d*C_MID+c];
        hs[lp][k][c] = fmaxf(acc, 0.0f);
    }
    __syncthreads();

    // lift = relu(h @ d2 + b2)
    for (int k = 0; k < KNN; k++) {
        float acc = d2bs[c];
        const float4* hv = (const float4*)&hs[lp][k][0];
        #pragma unroll
        for (int i4 = 0; i4 < C_MID/4; i4++) {
            float4 h4 = hv[i4];
            acc += h4.x * d2s[(i4*4+0)*C_MID + c];
            acc += h4.y * d2s[(i4*4+1)*C_MID + c];
            acc += h4.z * d2s[(i4*4+2)*C_MID + c];
            acc += h4.w * d2s[(i4*4+3)*C_MID + c];
        }
        g_lift[((size_t)pt*KNN + k)*C_MID + c] = fmaxf(acc, 0.0f);
    }
}

// ---------------- stage 2: X-transform (cv -> x1 -> x2) -> g_X ----------------
// block = 256 threads (thread j owns output column j), 16 points per block
#define XF_TP 16
#define XF_SMEM_FLOATS (DIMS*KNN*KK2 + KK2 + KK2 + KK2 + XF_TP*48 + XF_TP*KK2 + XF_TP*KK2)
__global__ void k_xform(const float* __restrict__ rep, const float* __restrict__ pts,
                        const float* __restrict__ cvw, const float* __restrict__ cvb,
                        const float* __restrict__ x1w, const float* __restrict__ x1b,
                        const float* __restrict__ x2w, const float* __restrict__ x2b) {
    extern __shared__ float sm[];
    float* cv_s  = sm;                       // [48][256] transposed; r = d*16 + k
    float* cvb_s = cv_s  + DIMS*KNN*KK2;     // 256
    float* x1b_s = cvb_s + KK2;
    float* x2b_s = x1b_s + KK2;
    float* pls   = x2b_s + KK2;              // [16][48]; r = d*16 + k  (MATCHES cv_s)
    float* X0s   = pls   + XF_TP*48;         // [16][256]
    float* X1s   = X0s   + XF_TP*KK2;        // [16][256]

    int j = threadIdx.x;
    // stage cv_w transposed: cvw[o*48 + r] -> cv_s[r*256 + o], r = d*16+k (native layout)
    for (int idx = j; idx < KK2*48; idx += 256) {
        int o = idx / 48, r = idx % 48;
        cv_s[r*KK2 + o] = cvw[idx];
    }
    cvb_s[j] = cvb[j]; x1b_s[j] = x1b[j]; x2b_s[j] = x2b[j];

    int p0 = blockIdx.x * XF_TP;
    // stage pls with r = d*16 + k so it pairs correctly with cv_s.
    for (int idx = j; idx < XF_TP*48; idx += 256) {
        int t = idx / 48, r = idx % 48;
        int d = r / KNN, k = r % KNN;
        int pt = p0 + t;
        pls[idx] = pts[((size_t)pt*KNN + k)*DIMS + d] - rep[(size_t)pt*DIMS + d];
    }
    __syncthreads();

    // X0 = relu(einsum(pl, cv) + cvb):  sum_r pl[d,k] * cv_w[j][d][k]
    for (int t = 0; t < XF_TP; t++) {
        float acc = cvb_s[j];
        #pragma unroll
        for (int r = 0; r < 48; r++) acc += pls[t*48 + r] * cv_s[r*KK2 + j];
        X0s[t*KK2 + j] = fmaxf(acc, 0.0f);
    }
    __syncthreads();

    // X1 = relu(X0 @ x1w + x1b)
    {
        float acc[XF_TP];
        #pragma unroll
        for (int t = 0; t < XF_TP; t++) acc[t] = x1b_s[j];
        for (int i = 0; i < KK2; i += 4) {
            float w0 = x1w[(i+0)*KK2 + j];
            float w1 = x1w[(i+1)*KK2 + j];
            float w2 = x1w[(i+2)*KK2 + j];
            float w3 = x1w[(i+3)*KK2 + j];
            #pragma unroll
            for (int t = 0; t < XF_TP; t++) {
                float4 x4 = *(const float4*)&X0s[t*KK2 + i];
                acc[t] += x4.x*w0 + x4.y*w1 + x4.z*w2 + x4.w*w3;
            }
        }
        #pragma unroll
        for (int t = 0; t < XF_TP; t++) X1s[t*KK2 + j] = fmaxf(acc[t], 0.0f);
    }
    __syncthreads();

    // X2 = X1 @ x2w + x2b   (no relu) -> g_X
    {
        float acc[XF_TP];
        #pragma unroll
        for (int t = 0; t < XF_TP; t++) acc[t] = x2b_s[j];
        for (int i = 0; i < KK2; i += 4) {
            float w0 = x2w[(i+0)*KK2 + j];
            float w1 = x2w[(i+1)*KK2 + j];
            float w2 = x2w[(i+2)*KK2 + j];
            float w3 = x2w[(i+3)*KK2 + j];
            #pragma unroll
            for (int t = 0; t < XF_TP; t++) {
                float4 x4 = *(const float4*)&X1s[t*KK2 + i];
                acc[t] += x4.x*w0 + x4.y*w1 + x4.z*w2 + x4.w*w3;
            }
        }
        #pragma unroll
        for (int t = 0; t < XF_TP; t++) g_X[((size_t)(p0+t))*KK2 + j] = acc[t];
    }
}

// ---------------- stage 3: fts_X -> depthwise -> pointwise -> relu, stats ----------------
// block = 256 threads, 16 points per block
#define AP_TP 16
#define AP_SMEM_FLOATS (AP_TP*KK2 + AP_TP*(C_CAT*DMUL) + C_CAT*33 + C_CAT*DMUL)
__global__ void k_apply(const float* __restrict__ fts,
                        const float* __restrict__ dww, const float* __restrict__ dwb) {
    extern __shared__ float sm[];
    float* Xs    = sm;                         // [16][256]
    float* dws   = Xs    + AP_TP*KK2;          // [16][384]
    float* dww_s = dws   + AP_TP*(C_CAT*DMUL); // [192][33] padded
    float* dwb_s = dww_s + C_CAT*33;           // [384]

    int tid = threadIdx.x;
    int p0 = blockIdx.x * AP_TP;

    for (int idx = tid; idx < AP_TP*KK2; idx += 256)
        Xs[idx] = g_X[(size_t)p0*KK2 + idx];
    for (int idx = tid; idx < C_CAT*DMUL*KNN; idx += 256) {
        int c = idx >> 5, r = idx & 31;        // r = m*16+k
        dww_s[c*33 + r] = dww[idx];
    }
    for (int idx = tid; idx < C_CAT*DMUL; idx += 256) dwb_s[idx] = dwb[idx];
    __syncthreads();

    // per-channel depthwise path: thread c (<192) handles cat channel c
    int c = tid;
    for (int t = 0; t < AP_TP; t++) {
        if (c < C_CAT) {
            int pt = p0 + t;
            float catv[KNN];
            if (c < C_MID) {
                #pragma unroll
                for (int jj = 0; jj < KNN; jj++)
                    catv[jj] = g_lift[((size_t)pt*KNN + jj)*C_MID + c];
            } else {
                #pragma unroll
                for (int jj = 0; jj < KNN; jj++)
                    catv[jj] = fts[((size_t)pt*KNN + jj)*C_IN + (c - C_MID)];
            }
            float dw0 = dwb_s[c*2 + 0];
            float dw1 = dwb_s[c*2 + 1];
            #pragma unroll
            for (int i = 0; i < KNN; i++) {
                float fx = 0.0f;
                #pragma unroll
                for (int jj = 0; jj < KNN; jj += 4) {
                    float4 x4 = *(const float4*)&Xs[t*KK2 + i*KNN + jj];
                    fx += x4.x*catv[jj] + x4.y*catv[jj+1] + x4.z*catv[jj+2] + x4.w*catv[jj+3];
                }
                dw0 += fx * dww_s[c*33 + i];        // m=0
                dw1 += fx * dww_s[c*33 + 16 + i];   // m=1
            }
            dws[t*(C_CAT*DMUL) + c*2 + 0] = dw0;
            dws[t*(C_CAT*DMUL) + c*2 + 1] = dw1;
        }
    }
    __syncthreads();

    // pointwise: thread o owns out channel o
    int o = tid;
    float acc[AP_TP];
    #pragma unroll
    for (int t = 0; t < AP_TP; t++) acc[t] = 0.0f;
    for (int jj = 0; jj < C_CAT*DMUL; jj += 4) {
        float w0 = g_pwT[(jj+0)*C_OUT + o];
        float w1 = g_pwT[(jj+1)*C_OUT + o];
        float w2 = g_pwT[(jj+2)*C_OUT + o];
        float w3 = g_pwT[(jj+3)*C_OUT + o];
        #pragma unroll
        for (int t = 0; t < AP_TP; t++) {
            float4 d4 = *(const float4*)&dws[t*(C_CAT*DMUL) + jj];
            acc[t] += d4.x*w0 + d4.y*w1 + d4.z*w2 + d4.w*w3;
        }
    }
    float s = 0.0f, s2 = 0.0f;
    #pragma unroll
    for (int t = 0; t < AP_TP; t++) {
        float v = fmaxf(acc[t], 0.0f);
        g_pre[((size_t)(p0+t))*C_OUT + o] = v;
        s += v; s2 += v*v;
    }
    atomicAdd(&g_stats[o], s);
    atomicAdd(&g_stats[C_OUT + o], s2);
}

// ---------------- stage 4: BN finalize + apply ----------------
__global__ void k_stats(const float* __restrict__ bng, const float* __restrict__ bnb) {
    int o = threadIdx.x;
    float inv_n = 1.0f / (float)NP;
    float mean = g_stats[o] * inv_n;
    float var  = g_stats[C_OUT + o] * inv_n - mean*mean;
    float sc = bng[o] * rsqrtf(var + EPSV);
    g_scale[o] = sc;
    g_shift[o] = bnb[o] - mean * sc;
}

__global__ void k_bn(float* __restrict__ out) {
    size_t idx = (size_t)blockIdx.x * 256 + threadIdx.x;
    int o = (int)(idx & (C_OUT - 1));
    out[idx] = g_pre[idx] * g_scale[o] + g_shift[o];
}

// ---------------- launch ----------------
extern "C" void kernel_launch(void* const* d_in, const int* in_sizes, int n_in,
                              void* d_out, int out_size) {
    const float* rep = (const float*)d_in[0];
    const float* pts = (const float*)d_in[1];
    const float* fts = (const float*)d_in[2];
    const float* d1w = (const float*)d_in[3];
    const float* d1b = (const float*)d_in[4];
    const float* d2w = (const float*)d_in[5];
    const float* d2b = (const float*)d_in[6];
    const float* cvw = (const float*)d_in[7];
    const float* cvb = (const float*)d_in[8];
    const float* x1w = (const float*)d_in[9];
    const float* x1b = (const float*)d_in[10];
    const float* x2w = (const float*)d_in[11];
    const float* x2b = (const float*)d_in[12];
    const float* dww = (const float*)d_in[13];
    const float* dwb = (const float*)d_in[14];
    const float* pww = (const float*)d_in[15];
    const float* bng = (const float*)d_in[16];
    const float* bnb = (const float*)d_in[17];

    const int xf_smem = XF_SMEM_FLOATS * (int)sizeof(float);   // ~88 KB
    const int ap_smem = AP_SMEM_FLOATS * (int)sizeof(float);   // ~68 KB
    cudaFuncSetAttribute(k_xform, cudaFuncAttributeMaxDynamicSharedMemorySize, xf_smem);
    cudaFuncSetAttribute(k_apply, cudaFuncAttributeMaxDynamicSharedMemorySize, ap_smem);

    k_prep <<<(C_OUT*C_CAT*DMUL + 255)/256, 256>>>(pww);
    k_lift <<<NP/4, 256>>>(rep, pts, d1w, d1b, d2w, d2b);
    k_xform<<<NP/XF_TP, 256, xf_smem>>>(rep, pts, cvw, cvb, x1w, x1b, x2w, x2b);
    k_apply<<<NP/AP_TP, 256, ap_smem>>>(fts, dww, dwb);
    k_stats<<<1, C_OUT>>>(bng, bnb);
    k_bn   <<<NP, 256>>>((float*)d_out);
}